// round 15
// baseline (speedup 1.0000x reference)
#include <cuda_runtime.h>
#include <math.h>

#define N_NODES  50000
#define N_EDGES  800000
#define N_GRAPHS 512
#define IN_F     128
#define HEADS    8
#define OUT_F    64
#define NEG_SLOPE 0.2f
#define SCAN_BLOCKS 49   // ceil(50000/1024)

// ---------------- scratch ----------------
__device__ __align__(16) float g_h   [N_NODES * OUT_F];   // 12.8 MB
__device__ __align__(16) float g_as  [N_NODES * HEADS];
__device__ __align__(16) float g_ad  [N_NODES * HEADS];
__device__ __align__(16) float g_p   [N_NODES];
__device__ __align__(16) float g_score[N_NODES];
__device__ __align__(16) float g_gden [N_GRAPHS];
__device__ int g_batch[N_NODES];
__device__ int g_cnt  [N_NODES];
__device__ int g_incl [SCAN_BLOCKS * 1024];
__device__ int g_bsum [SCAN_BLOCKS];
__device__ int g_bbase[SCAN_BLOCKS];
__device__ int g_offs [N_NODES + 1];
__device__ int g_cursor[N_NODES];
__device__ int g_csr  [N_EDGES];
__device__ int g_eflag;
__device__ int g_scan_done;

// ---------------- helpers ----------------
__device__ __forceinline__ float lrelu(float v) { return fmaxf(v, NEG_SLOPE * v); }

__device__ __forceinline__ void red_add_v4(float* addr, float4 v) {
    asm volatile("red.global.add.v4.f32 [%0], {%1,%2,%3,%4};"
                 :: "l"(addr), "f"(v.x), "f"(v.y), "f"(v.z), "f"(v.w) : "memory");
}

// packed 2xfp32 FMA (sm_100+): d = a*b + c elementwise on 64-bit packed pairs
#define FMA2(d, a, b, c) \
    asm("fma.rn.f32x2 %0, %1, %2, %3;" : "=l"(d) : "l"(a), "l"(b), "l"(c))

__device__ __forceinline__ float2 unpack2(unsigned long long v) {
    float2 f;
    asm("mov.b64 {%0, %1}, %2;" : "=f"(f.x), "=f"(f.y) : "l"(v));
    return f;
}

__device__ __forceinline__ int detect_e64(const void* ei) {
    const long long* e64 = (const long long*)ei;
    int ok = 1;
    #pragma unroll
    for (int i = 0; i < 16; i++) {
        long long v = e64[(long long)i * 49999 + 3];
        if (v < 0 || v >= N_NODES) ok = 0;
    }
    return ok;
}
__device__ __forceinline__ int detect_b64(const void* batch) {
    const long long* b64 = (const long long*)batch;
    int ok = 1;
    #pragma unroll
    for (int i = 0; i < 16; i++) {
        long long v = b64[(long long)i * 1499 + 11];
        if (v < 0 || v >= N_GRAPHS) ok = 0;
    }
    return ok;
}

// ---------------- K0: node init ----------------
__global__ void k0_nodes(const void* batch)
{
    __shared__ int sb;
    int tid = threadIdx.x;
    if (tid == 0) {
        sb = detect_b64(batch);
        if (blockIdx.x == 0) g_scan_done = 0;
    }
    __syncthreads();
    int i = blockIdx.x * 256 + tid;
    if (i >= N_NODES) return;
    g_cnt[i] = 0;
    if (sb) g_batch[i] = (int)((const long long*)batch)[i];
    else    g_batch[i] = ((const int*)batch)[i];
}

// ---------------- K_hist: dst histogram ----------------
__global__ void k_hist(const void* ei)
{
    __shared__ int se;
    int tid = threadIdx.x;
    if (tid == 0) {
        se = detect_e64(ei);
        if (blockIdx.x == 0) g_eflag = se;
    }
    __syncthreads();
    int i = blockIdx.x * 256 + tid;
    if (i >= N_EDGES) return;
    int d;
    if (se) d = (int)((const long long*)ei)[N_EDGES + i];
    else    d = ((const int*)ei)[N_EDGES + i];
    atomicAdd(&g_cnt[d], 1);
}

// ---------------- K_scan1 ----------------
__global__ void k_scan1()
{
    __shared__ int sdata[1024];
    __shared__ int is_last;
    int tid = threadIdx.x;
    int idx = blockIdx.x * 1024 + tid;
    int v = (idx < N_NODES) ? g_cnt[idx] : 0;
    sdata[tid] = v;
    __syncthreads();
    #pragma unroll
    for (int off = 1; off < 1024; off <<= 1) {
        int t = (tid >= off) ? sdata[tid - off] : 0;
        __syncthreads();
        sdata[tid] += t;
        __syncthreads();
    }
    g_incl[idx] = sdata[tid];

    if (tid == 0) {
        g_bsum[blockIdx.x] = sdata[1023];
        __threadfence();
        int done = atomicAdd(&g_scan_done, 1);
        is_last = (done == SCAN_BLOCKS - 1);
    }
    __syncthreads();
    if (is_last) {
        int val = (tid < SCAN_BLOCKS) ? g_bsum[tid] : 0;
        sdata[tid] = (tid < 64) ? val : 0;
        __syncthreads();
        #pragma unroll
        for (int off = 1; off < 64; off <<= 1) {
            int t = (tid >= off && tid < 64) ? sdata[tid - off] : 0;
            __syncthreads();
            if (tid < 64) sdata[tid] += t;
            __syncthreads();
        }
        if (tid < SCAN_BLOCKS) g_bbase[tid] = sdata[tid] - val;
    }
}

// ---------------- K_scan3 ----------------
__global__ void k_scan3(float* __restrict__ gout)
{
    int idx = blockIdx.x * blockDim.x + threadIdx.x;
    if (idx < N_GRAPHS * OUT_F) gout[idx] = 0.f;
    if (idx < N_GRAPHS) g_gden[idx] = 0.f;
    if (idx >= N_NODES) return;
    int excl = g_incl[idx] - g_cnt[idx] + g_bbase[idx >> 10];
    g_offs[idx]   = excl;
    g_cursor[idx] = excl;
    if (idx == 0) g_offs[N_NODES] = N_EDGES;
}

// ---------------- K_fill ----------------
__global__ void k_fill(const void* ei)
{
    int e = blockIdx.x * blockDim.x + threadIdx.x;
    if (e >= N_EDGES) return;
    int s, d;
    if (g_eflag) {
        const long long* e64 = (const long long*)ei;
        s = (int)e64[e];
        d = (int)e64[N_EDGES + e];
    } else {
        const int* e32 = (const int*)ei;
        s = e32[e];
        d = e32[N_EDGES + e];
    }
    int pos = atomicAdd(&g_cursor[d], 1);
    g_csr[pos] = s;
}

// ---------------- K1: FFMA2 GEMM (k-pair packed) + fused attention logits ----------------
// tile: 128 nodes x 64 cols, 256 threads, thread tile 8 nodes x 4 cols (packed over k-parity)
#define GM 128
#define KS 16
#define XP2 264   // floats per kk2-row of sx2 (128*2 + 8); 1056B, 16B-aligned
#define WP2 136   // floats per kk2-row of sw2 (64*2 + 8); 544B, 16B-aligned
__global__ void __launch_bounds__(256) k1_gemm(const float* __restrict__ x,
                                               const float* __restrict__ W,
                                               const float* __restrict__ att_src,
                                               const float* __restrict__ att_dst)
{
    __shared__ __align__(16) float sx2[(KS/2) * XP2];   // ~8.4 KB
    __shared__ __align__(16) float sw2[(KS/2) * WP2];   // ~4.4 KB
    int tid  = threadIdx.x;
    int trow = tid >> 4;     // 0..15 -> nodes trow*8 .. +7
    int tcol = tid & 15;     // 0..15 -> cols  tcol*4 .. +3
    int nb   = blockIdx.x * GM;

    unsigned long long acc2[8][4];
    #pragma unroll
    for (int r = 0; r < 8; r++)
        #pragma unroll
        for (int c = 0; c < 4; c++) acc2[r][c] = 0ULL;   // {0.f, 0.f}

    for (int k0 = 0; k0 < IN_F; k0 += KS) {
        // W tile: 16 k x 64 c, k-pair interleaved. 256 threads x 1 float4.
        {
            int k  = tid >> 4;      // 0..15
            int c4 = tid & 15;      // 0..15
            float4 wv = *(const float4*)&W[(k0 + k) * OUT_F + c4 * 4];
            float* dst = &sw2[(k >> 1) * WP2 + (k & 1)];
            dst[(c4 * 4 + 0) * 2] = wv.x;
            dst[(c4 * 4 + 1) * 2] = wv.y;
            dst[(c4 * 4 + 2) * 2] = wv.z;
            dst[(c4 * 4 + 3) * 2] = wv.w;
        }
        // x tile: 128 nodes x 16 k, k-pair interleaved. 2 float4 per thread.
        #pragma unroll
        for (int r = 0; r < 2; r++) {
            int j = r * 256 + tid;
            int node = j >> 2;      // 0..127
            int q = j & 3;          // k-quad
            int gn = nb + node; if (gn >= N_NODES) gn = N_NODES - 1;
            float4 xv = *(const float4*)&x[(long)gn * IN_F + k0 + q * 4];
            *(float2*)&sx2[(q * 2)     * XP2 + node * 2] = make_float2(xv.x, xv.y);
            *(float2*)&sx2[(q * 2 + 1) * XP2 + node * 2] = make_float2(xv.z, xv.w);
        }
        __syncthreads();
        #pragma unroll
        for (int kk2 = 0; kk2 < KS / 2; kk2++) {
            const ulonglong2* xp = (const ulonglong2*)&sx2[kk2 * XP2 + trow * 16];
            ulonglong2 xa = xp[0], xb = xp[1], xc = xp[2], xd = xp[3];
            const ulonglong2* wp = (const ulonglong2*)&sw2[kk2 * WP2 + tcol * 8];
            ulonglong2 wa = wp[0], wb = wp[1];
            unsigned long long xs[8] = {xa.x, xa.y, xb.x, xb.y, xc.x, xc.y, xd.x, xd.y};
            unsigned long long ws[4] = {wa.x, wa.y, wb.x, wb.y};
            #pragma unroll
            for (int r = 0; r < 8; r++)
                #pragma unroll
                for (int c = 0; c < 4; c++)
                    FMA2(acc2[r][c], xs[r], ws[c], acc2[r][c]);
        }
        __syncthreads();
    }

    // epilogue: horizontal add of k-parity halves, store h, fused attention logits
    int head = tcol >> 1;
    float4 asv = *(const float4*)&att_src[tcol * 4];
    float4 adv = *(const float4*)&att_dst[tcol * 4];
    #pragma unroll
    for (int r = 0; r < 8; r++) {
        float2 f0 = unpack2(acc2[r][0]);
        float2 f1 = unpack2(acc2[r][1]);
        float2 f2 = unpack2(acc2[r][2]);
        float2 f3 = unpack2(acc2[r][3]);
        float4 hv = make_float4(f0.x + f0.y, f1.x + f1.y, f2.x + f2.y, f3.x + f3.y);
        int gn = nb + trow * 8 + r;
        bool ok = (gn < N_NODES);
        if (ok) *(float4*)&g_h[(long)gn * OUT_F + tcol * 4] = hv;

        float vs = hv.x * asv.x + hv.y * asv.y + hv.z * asv.z + hv.w * asv.w;
        float vd = hv.x * adv.x + hv.y * adv.y + hv.z * adv.z + hv.w * adv.w;
        vs += __shfl_xor_sync(0xffffffffu, vs, 1);
        vd += __shfl_xor_sync(0xffffffffu, vd, 1);
        if (ok && (tcol & 1) == 0) {
            g_as[gn * 8 + head] = vs;
            g_ad[gn * 8 + head] = vd;
        }
    }
}

// ---------------- K_agg: half-warp x float4 — 2 edges per warp instruction ----------------
__global__ void k_agg(float* __restrict__ out, const float* __restrict__ bias,
                      const float* __restrict__ wrel, const float* __restrict__ brel,
                      const float* __restrict__ wroot)
{
    int warp = threadIdx.x >> 5, lane = threadIdx.x & 31;
    int n = blockIdx.x * 8 + warp;
    if (n >= N_NODES) return;
    int half = lane >> 4;       // 0 or 1
    int hl   = lane & 15;       // 0..15
    int head = hl >> 1;         // 0..7
    int c4   = hl * 4;          // column base

    float ad = g_ad[n * 8 + head];

    float den = 0.f;
    float4 acc = make_float4(0.f, 0.f, 0.f, 0.f);

    if (half == 0) {   // self-loop handled once, by half 0
        float e = __expf(lrelu(g_as[n * 8 + head] + ad));
        den = e;
        float4 hv = *(const float4*)&g_h[n * 64 + c4];
        acc.x = e * hv.x; acc.y = e * hv.y; acc.z = e * hv.z; acc.w = e * hv.w;
    }

    int beg = g_offs[n], end = g_offs[n + 1];
    int j = beg + half;
    for (; j + 6 < end; j += 8) {
        int s0 = g_csr[j];
        int s1 = g_csr[j + 2];
        int s2 = g_csr[j + 4];
        int s3 = g_csr[j + 6];
        float a0 = g_as[s0 * 8 + head];
        float a1 = g_as[s1 * 8 + head];
        float a2 = g_as[s2 * 8 + head];
        float a3 = g_as[s3 * 8 + head];
        float4 h0 = *(const float4*)&g_h[s0 * 64 + c4];
        float4 h1 = *(const float4*)&g_h[s1 * 64 + c4];
        float4 h2 = *(const float4*)&g_h[s2 * 64 + c4];
        float4 h3 = *(const float4*)&g_h[s3 * 64 + c4];
        float e0 = __expf(lrelu(a0 + ad));
        float e1 = __expf(lrelu(a1 + ad));
        float e2 = __expf(lrelu(a2 + ad));
        float e3 = __expf(lrelu(a3 + ad));
        den += (e0 + e1) + (e2 + e3);
        acc.x = fmaf(e0, h0.x, fmaf(e1, h1.x, fmaf(e2, h2.x, fmaf(e3, h3.x, acc.x))));
        acc.y = fmaf(e0, h0.y, fmaf(e1, h1.y, fmaf(e2, h2.y, fmaf(e3, h3.y, acc.y))));
        acc.z = fmaf(e0, h0.z, fmaf(e1, h1.z, fmaf(e2, h2.z, fmaf(e3, h3.z, acc.z))));
        acc.w = fmaf(e0, h0.w, fmaf(e1, h1.w, fmaf(e2, h2.w, fmaf(e3, h3.w, acc.w))));
    }
    for (; j < end; j += 2) {
        int s = g_csr[j];
        float e = __expf(lrelu(g_as[s * 8 + head] + ad));
        den += e;
        float4 hv = *(const float4*)&g_h[s * 64 + c4];
        acc.x = fmaf(e, hv.x, acc.x);
        acc.y = fmaf(e, hv.y, acc.y);
        acc.z = fmaf(e, hv.z, acc.z);
        acc.w = fmaf(e, hv.w, acc.w);
    }

    den   += __shfl_xor_sync(0xffffffffu, den,   16);
    acc.x += __shfl_xor_sync(0xffffffffu, acc.x, 16);
    acc.y += __shfl_xor_sync(0xffffffffu, acc.y, 16);
    acc.z += __shfl_xor_sync(0xffffffffu, acc.z, 16);
    acc.w += __shfl_xor_sync(0xffffffffu, acc.w, 16);

    if (half == 0) {
        float inv = 1.f / (den + 1e-16f);
        float4 bv = *(const float4*)&bias[c4];
        float4 ov;
        ov.x = bv.x + acc.x * inv;
        ov.y = bv.y + acc.y * inv;
        ov.z = bv.z + acc.z * inv;
        ov.w = bv.w + acc.w * inv;
        *(float4*)&out[n * 64 + c4] = ov;

        float4 wr = *(const float4*)&wrel[c4];
        float4 wq = *(const float4*)&wroot[c4];
        float vr = ov.x * wr.x + ov.y * wr.y + ov.z * wr.z + ov.w * wr.w;
        float vq = ov.x * wq.x + ov.y * wq.y + ov.z * wq.z + ov.w * wq.w;
        #pragma unroll
        for (int off = 8; off; off >>= 1) {
            vr += __shfl_xor_sync(0x0000ffffu, vr, off);
            vq += __shfl_xor_sync(0x0000ffffu, vq, off);
        }
        if (hl == 0) {
            g_p[n]     = vr;
            g_score[n] = brel[0] + vq;
        }
    }
}

// ---------------- K7: score aggregation via CSR + fused exp/gden ----------------
__global__ void k7_score_gexp()
{
    int warp = threadIdx.x >> 5, lane = threadIdx.x & 31;
    int n = blockIdx.x * 8 + warp;
    if (n >= N_NODES) return;
    int beg = g_offs[n], end = g_offs[n + 1];
    float acc = 0.f;
    for (int j = beg + lane; j < end; j += 32) acc += g_p[g_csr[j]];
    #pragma unroll
    for (int off = 16; off; off >>= 1) acc += __shfl_xor_sync(0xffffffffu, acc, off);
    if (lane == 0) {
        float ex = __expf(g_score[n] + acc);   // scores O(±10): unshifted exp safe
        g_score[n] = ex;
        atomicAdd(&g_gden[g_batch[n]], ex);
    }
}

// ---------------- K10: pooled output, 8 nodes/thread w/ register accumulation ----------------
__global__ void k10_gpool(const float* __restrict__ out, float* __restrict__ gout)
{
    int t = blockIdx.x * blockDim.x + threadIdx.x;   // 100000 threads
    if (t >= 100000) return;
    int q   = t & 15;
    int n0  = (t >> 4) * 8;

    float4 acc = make_float4(0.f, 0.f, 0.f, 0.f);
    int curg = g_batch[n0];
    float inv = 1.f / (g_gden[curg] + 1e-16f);
    #pragma unroll
    for (int i = 0; i < 8; i++) {
        int n = n0 + i;
        int g = g_batch[n];
        if (g != curg) {
            red_add_v4(&gout[curg * 64 + q * 4], acc);
            acc = make_float4(0.f, 0.f, 0.f, 0.f);
            curg = g;
            inv = 1.f / (g_gden[curg] + 1e-16f);
        }
        float s = g_score[n] * inv;
        float4 v = *(const float4*)&out[(long)n * 64 + q * 4];
        acc.x = fmaf(v.x, s, acc.x);
        acc.y = fmaf(v.y, s, acc.y);
        acc.z = fmaf(v.z, s, acc.z);
        acc.w = fmaf(v.w, s, acc.w);
    }
    red_add_v4(&gout[curg * 64 + q * 4], acc);
}

// ---------------- launch ----------------
extern "C" void kernel_launch(void* const* d_in, const int* in_sizes, int n_in,
                              void* d_out, int out_size)
{
    const float* x = 0; const void* ei = 0; const void* batch = 0;
    const float* W = 0; const float* brel = 0;
    const float* f64s[5] = {0,0,0,0,0};
    int n64 = 0;
    for (int i = 0; i < n_in; i++) {
        long long sz = in_sizes[i];
        if      (sz == (long long)N_NODES * IN_F) x     = (const float*)d_in[i];
        else if (sz == (long long)2 * N_EDGES)    ei    = d_in[i];
        else if (sz == N_NODES)                   batch = d_in[i];
        else if (sz == IN_F * OUT_F)              W     = (const float*)d_in[i];
        else if (sz == 1)                         brel  = (const float*)d_in[i];
        else if (sz == OUT_F && n64 < 5)          f64s[n64++] = (const float*)d_in[i];
    }
    const float* asrc  = f64s[0];
    const float* adst  = f64s[1];
    const float* bias  = f64s[2];
    const float* wrel  = f64s[3];
    const float* wroot = f64s[4];

    float* out  = (float*)d_out;
    float* gout = out + (long)N_NODES * OUT_F;

    k0_nodes<<<(N_NODES + 255) / 256, 256>>>(batch);              // 1
    k_hist<<<(N_EDGES + 255) / 256, 256>>>(ei);                   // 2
    k_scan1<<<SCAN_BLOCKS, 1024>>>();                             // 3
    k1_gemm<<<(N_NODES + GM - 1) / GM, 256>>>(x, W, asrc, adst);  // 4 <- ncu capture slot
    k_scan3<<<(N_NODES + 255) / 256, 256>>>(gout);                // 5
    k_fill<<<(N_EDGES + 255) / 256, 256>>>(ei);                   // 6
    k_agg<<<(N_NODES + 7) / 8, 256>>>(out, bias, wrel, brel, wroot); // 7
    k7_score_gexp<<<(N_NODES + 7) / 8, 256>>>();                  // 8
    k10_gpool<<<(100000 + 255) / 256, 256>>>(out, gout);          // 9
}